// round 15
// baseline (speedup 1.0000x reference)
#include <cuda_runtime.h>
#include <cuda_fp16.h>
#include <cstdint>
#include <math.h>

#define B_ 16
#define T_ 1024
#define D_ 1024
#define TD (T_ * D_)

typedef __half f16;

// ---------------- scratch (device globals; no allocations) ----------------
static __device__ f16  g_X16[B_ * TD];     // fp16(x)
static __device__ f16  g_Wq16[D_ * D_];
static __device__ f16  g_Wk16[D_ * D_];
static __device__ f16  g_Wv16[D_ * D_];
static __device__ f16  g_W216[TD];         // fp16(Wfc) viewed [q, d]
static __device__ f16  g_N116[D_ * D_];    // fp16( (1/32) Wq.Wk^T )
static __device__ f16  g_N216[TD];         // fp16( W2.Wv^T )
static __device__ f16  g_Y16[B_ * TD];     // fp16( X.N1^T )
static __device__ f16  g_C16[B_ * TD];     // fp16( X.N2^T ) per batch
static __device__ float g_S[(size_t)B_ * T_ * T_];
static __device__ float g_u[D_];           // (1/32) Wq.bk
static __device__ float g_c[B_ * T_];      // x_t.u
static __device__ float g_r2[T_];          // bv.W2[q]
static __device__ float g_rowsum[B_ * T_];

// ---------------- low-level helpers ----------------
__device__ __forceinline__ uint32_t smem_u32(const void* p) {
    uint32_t a;
    asm("{ .reg .u64 t; cvta.to.shared.u64 t, %1; cvt.u32.u64 %0, t; }"
        : "=r"(a) : "l"(p));
    return a;
}
__device__ __forceinline__ void cpa16(uint32_t s, const void* g) {
    asm volatile("cp.async.cg.shared.global [%0], [%1], 16;" :: "r"(s), "l"(g));
}
__device__ __forceinline__ void cpa_commit() {
    asm volatile("cp.async.commit_group;" ::: "memory");
}
__device__ __forceinline__ void cpa_wait1() {
    asm volatile("cp.async.wait_group 1;" ::: "memory");
}
__device__ __forceinline__ void cpa_wait0() {
    asm volatile("cp.async.wait_group 0;" ::: "memory");
}
__device__ __forceinline__ void ldsm4(uint32_t (&r)[4], uint32_t addr) {
    asm volatile("ldmatrix.sync.aligned.m8n8.x4.shared.b16 {%0,%1,%2,%3}, [%4];"
        : "=r"(r[0]), "=r"(r[1]), "=r"(r[2]), "=r"(r[3]) : "r"(addr));
}
__device__ __forceinline__ void mma16816h(float* d, const uint32_t* a,
                                          uint32_t b0, uint32_t b1) {
    asm volatile(
        "mma.sync.aligned.m16n8k16.row.col.f32.f16.f16.f32 "
        "{%0,%1,%2,%3}, {%4,%5,%6,%7}, {%8,%9}, {%0,%1,%2,%3};"
        : "+f"(d[0]), "+f"(d[1]), "+f"(d[2]), "+f"(d[3])
        : "r"(a[0]), "r"(a[1]), "r"(a[2]), "r"(a[3]), "r"(b0), "r"(b1));
}
__device__ __forceinline__ unsigned short hbits(f16 h) {
    return *reinterpret_cast<unsigned short*>(&h);
}

// ---------------- merged split kernel: everything -> fp16 -----------------
#define N4_X   (B_ * TD / 4)
#define N4_W   (D_ * D_ / 4)
#define N4_ALL (N4_X + 4 * N4_W)

__global__ void split_all(const float* __restrict__ x, const float* __restrict__ Wq,
                          const float* __restrict__ Wk, const float* __restrict__ Wv,
                          const float* __restrict__ Wfc) {
    int i = blockIdx.x * blockDim.x + threadIdx.x;
    if (i >= N4_ALL) return;
    int j = i;
    const float* src;
    f16* dst;
    if (j < N4_X) { src = x; dst = g_X16; }
    else {
        j -= N4_X;
        if (j < N4_W)          { src = Wq;  dst = g_Wq16; }
        else if (j < 2 * N4_W) { j -= N4_W;     src = Wk;  dst = g_Wk16; }
        else if (j < 3 * N4_W) { j -= 2 * N4_W; src = Wv;  dst = g_Wv16; }
        else                   { j -= 3 * N4_W; src = Wfc; dst = g_W216; }
    }
    float4 v = ((const float4*)src)[j];
    f16 h0 = __float2half_rn(v.x), h1 = __float2half_rn(v.y);
    f16 h2 = __float2half_rn(v.z), h3 = __float2half_rn(v.w);
    ((ushort4*)dst)[j] = make_ushort4(hbits(h0), hbits(h1), hbits(h2), hbits(h3));
}

// ---------------- GEMV kernels (warp per row, fp32) ----------------
__global__ void gemv_ur(const float* __restrict__ Wq, const float* __restrict__ bk,
                        const float* __restrict__ Wfc, const float* __restrict__ bv) {
    int warp = threadIdx.x >> 5, lane = threadIdx.x & 31;
    const float *mat, *vec;
    float* dst;
    float scale;
    int row;
    if (blockIdx.x < 128) { mat = Wq;  vec = bk; dst = g_u;  scale = 0.03125f; row = blockIdx.x * 8 + warp; }
    else                  { mat = Wfc; vec = bv; dst = g_r2; scale = 1.0f;     row = (blockIdx.x - 128) * 8 + warp; }
    const float4* w4 = (const float4*)(mat + (size_t)row * D_);
    const float4* b4 = (const float4*)vec;
    float s = 0.f;
#pragma unroll
    for (int i = 0; i < 8; i++) {
        float4 w = w4[lane + i * 32], b = b4[lane + i * 32];
        s += w.x * b.x + w.y * b.y + w.z * b.z + w.w * b.w;
    }
#pragma unroll
    for (int o = 16; o; o >>= 1) s += __shfl_xor_sync(0xffffffffu, s, o);
    if (lane == 0) dst[row] = s * scale;
}

__global__ void gemv_c(const float* __restrict__ x) {
    int warp = threadIdx.x >> 5, lane = threadIdx.x & 31;
    int row = blockIdx.x * 8 + warp;   // 0..16383
    const float4* x4 = (const float4*)(x + (size_t)row * D_);
    const float4* u4 = (const float4*)g_u;
    float s = 0.f;
#pragma unroll
    for (int i = 0; i < 8; i++) {
        float4 w = x4[lane + i * 32], b = u4[lane + i * 32];
        s += w.x * b.x + w.y * b.y + w.z * b.z + w.w * b.w;
    }
#pragma unroll
    for (int o = 16; o; o >>= 1) s += __shfl_xor_sync(0xffffffffu, s, o);
    if (lane == 0) g_c[row] = s;
}

// ===================== fp16 mainloop v2: CTA 256x128 =======================
// 8 warps (4x2), warp tile 64x64, ktile 64 (4 x k16), 2-stage cp.async, occ 1.
// Crossbar traffic per MAC reduced ~12% vs 128x128 pairs.
// Correct double-barrier ordering; A-fragment double buffering.
#define NT 256
#define LDB16 144            // 128B row + 16B pad -> conflict-free ldmatrix
#define OPA (256 * LDB16)    // 36864 (A: 256 rows)
#define OPB2 (128 * LDB16)   // 18432 (B: 128 rows)
#define STG (OPA + OPB2)     // 55296
#define DYN (2 * STG)        // 110592

__device__ __forceinline__ void load_stage16(uint32_t sb,
        const f16* __restrict__ A, const f16* __restrict__ Bm,
        int rowBase, int colBase, int kt, int tid) {
    // A: 256 rows x 128B = 2048 16B-chunks
#pragma unroll
    for (int i = 0; i < 8; i++) {
        int chunk = tid + i * NT;
        int row = chunk >> 3, c = chunk & 7;
        cpa16(sb + row * LDB16 + c * 16,
              A + (size_t)(rowBase + row) * D_ + kt * 64 + c * 8);
    }
    // B: 128 rows x 128B = 1024 chunks
#pragma unroll
    for (int i = 0; i < 4; i++) {
        int chunk = tid + i * NT;
        int row = chunk >> 3, c = chunk & 7;
        cpa16(sb + OPA + row * LDB16 + c * 16,
              Bm + (size_t)(colBase + row) * D_ + kt * 64 + c * 8);
    }
}

// acc[im 0..3][in 0..7][4]; warp (wm 0..3, wn 0..1)
__device__ __forceinline__ void gemm16_ml(uint32_t sbase,
        const f16* __restrict__ A, const f16* __restrict__ Bm,
        int rowBase, int colBase, int tid, float acc[4][8][4]) {
    const int lane = tid & 31, wid = tid >> 5;
    const int wm = wid & 3, wn = wid >> 2;
    const int lrow = lane & 15;
    const int lcol = (lane >> 4) * 16;

#pragma unroll
    for (int im = 0; im < 4; im++)
#pragma unroll
        for (int in = 0; in < 8; in++)
#pragma unroll
            for (int j = 0; j < 4; j++) acc[im][in][j] = 0.f;

    load_stage16(sbase, A, Bm, rowBase, colBase, 0, tid);
    cpa_commit();

    for (int kt = 0; kt < 16; kt++) {       // 16 ktiles of 64
        if (kt + 1 < 16) {
            load_stage16(sbase + ((kt + 1) & 1) * STG, A, Bm,
                         rowBase, colBase, kt + 1, tid);
            cpa_commit();
            cpa_wait1();
        } else {
            cpa_wait0();
        }
        __syncthreads();          // publish stage kt

        uint32_t st = sbase + (kt & 1) * STG;
        uint32_t aA = st + (wm * 64 + lrow) * LDB16 + lcol;
        uint32_t aB = st + OPA + (wn * 64 + lrow) * LDB16 + lcol;
#pragma unroll
        for (int kk = 0; kk < 4; kk++) {
            uint32_t bh[4][4];
            uint32_t ahb[2][4];
            ldsm4(ahb[0], aA + kk * 32);
#pragma unroll
            for (int g = 0; g < 4; g++)
                ldsm4(bh[g], aB + g * 16 * LDB16 + kk * 32);
#pragma unroll
            for (int im = 0; im < 4; im++) {
                const int cur = im & 1, nxt = cur ^ 1;
                if (im < 3)
                    ldsm4(ahb[nxt], aA + (im + 1) * 16 * LDB16 + kk * 32);
#pragma unroll
                for (int g = 0; g < 4; g++) {
                    mma16816h(acc[im][g * 2 + 0], ahb[cur], bh[g][0], bh[g][2]);
                    mma16816h(acc[im][g * 2 + 1], ahb[cur], bh[g][1], bh[g][3]);
                }
            }
        }
        __syncthreads();          // WAR: stage free
    }
}

// ---------------- N folds (fp16): grid (8,4,2) ----------------
// z=0: N116 = fp16((1/32) Wq.Wk^T) ; z=1: N216 = fp16(W2.Wv^T)
__global__ void __launch_bounds__(NT, 1)
nfold16() {
    extern __shared__ char dyn[];
    uint32_t sbase = smem_u32(dyn);
    const int tid = threadIdx.x;
    const int lane = tid & 31, wid = tid >> 5;
    const int wm = wid & 3, wn = wid >> 2;
    const int rowBase = blockIdx.y * 256, colBase = blockIdx.x * 128;

    const f16 *A, *Bm;
    f16* O;
    float scale;
    if (blockIdx.z == 0) { A = g_Wq16; Bm = g_Wk16; O = g_N116; scale = 0.03125f; }
    else                 { A = g_W216; Bm = g_Wv16; O = g_N216; scale = 1.0f; }

    float acc[4][8][4];
    gemm16_ml(sbase, A, Bm, rowBase, colBase, tid, acc);

#pragma unroll
    for (int in = 0; in < 8; in++) {
        int col = colBase + wn * 64 + in * 8 + (lane & 3) * 2;
#pragma unroll
        for (int im = 0; im < 4; im++) {
            int row0 = rowBase + wm * 64 + im * 16 + (lane >> 2);
            f16 h00 = __float2half_rn(acc[im][in][0] * scale);
            f16 h01 = __float2half_rn(acc[im][in][1] * scale);
            f16 h10 = __float2half_rn(acc[im][in][2] * scale);
            f16 h11 = __float2half_rn(acc[im][in][3] * scale);
            *(ushort2*)(O + (size_t)row0 * D_ + col) = make_ushort2(hbits(h00), hbits(h01));
            *(ushort2*)(O + (size_t)(row0 + 8) * D_ + col) = make_ushort2(hbits(h10), hbits(h11));
        }
    }
}

// ---------------- Y = fp16( X16 . N116^T ) : grid (8,64) ----------------
__global__ void __launch_bounds__(NT, 1)
y16_mma() {
    extern __shared__ char dyn[];
    uint32_t sbase = smem_u32(dyn);
    const int tid = threadIdx.x;
    const int lane = tid & 31, wid = tid >> 5;
    const int wm = wid & 3, wn = wid >> 2;
    const int rowBase = blockIdx.y * 256, colBase = blockIdx.x * 128;

    float acc[4][8][4];
    gemm16_ml(sbase, g_X16, g_N116, rowBase, colBase, tid, acc);

#pragma unroll
    for (int in = 0; in < 8; in++) {
        int col = colBase + wn * 64 + in * 8 + (lane & 3) * 2;
#pragma unroll
        for (int im = 0; im < 4; im++) {
            int row0 = rowBase + wm * 64 + im * 16 + (lane >> 2);
            f16 h00 = __float2half_rn(acc[im][in][0]);
            f16 h01 = __float2half_rn(acc[im][in][1]);
            f16 h10 = __float2half_rn(acc[im][in][2]);
            f16 h11 = __float2half_rn(acc[im][in][3]);
            *(ushort2*)(g_Y16 + (size_t)row0 * D_ + col) = make_ushort2(hbits(h00), hbits(h01));
            *(ushort2*)(g_Y16 + (size_t)(row0 + 8) * D_ + col) = make_ushort2(hbits(h10), hbits(h11));
        }
    }
}

// ---------------- st + C merged: grid (8, 4, 32) ----------------
// z = b + 16*job. job0: S[b][k][q] = Y16_b[k].X16_b[q] + c_b[q]  (fp32)
//                 job1: C16[b][k][q] = X16_b[k].N216[q]          (fp16)
__global__ void __launch_bounds__(NT, 1)
stc16_mma() {
    extern __shared__ char dyn[];
    uint32_t sbase = smem_u32(dyn);
    const int tid = threadIdx.x;
    const int lane = tid & 31, wid = tid >> 5;
    const int wm = wid & 3, wn = wid >> 2;
    const int b = blockIdx.z & 15;
    const int job = blockIdx.z >> 4;
    const int rowBase = blockIdx.y * 256, colBase = blockIdx.x * 128;

    const f16* A = job ? (g_X16 + (size_t)b * TD) : (g_Y16 + (size_t)b * TD);
    const f16* Bm = job ? g_N216 : (g_X16 + (size_t)b * TD);

    float acc[4][8][4];
    gemm16_ml(sbase, A, Bm, rowBase, colBase, tid, acc);

    if (job == 0) {
        float* __restrict__ S = g_S + (size_t)b * T_ * T_;
        const float* __restrict__ c = g_c + (size_t)b * T_;
#pragma unroll
        for (int in = 0; in < 8; in++) {
            int col = colBase + wn * 64 + in * 8 + (lane & 3) * 2;
            float2 cc = *(const float2*)(c + col);
#pragma unroll
            for (int im = 0; im < 4; im++) {
                int row0 = rowBase + wm * 64 + im * 16 + (lane >> 2);
                *(float2*)(S + (size_t)row0 * T_ + col) =
                    make_float2(acc[im][in][0] + cc.x, acc[im][in][1] + cc.y);
                *(float2*)(S + (size_t)(row0 + 8) * T_ + col) =
                    make_float2(acc[im][in][2] + cc.x, acc[im][in][3] + cc.y);
            }
        }
    } else {
        f16* __restrict__ C = g_C16 + (size_t)b * TD;
#pragma unroll
        for (int in = 0; in < 8; in++) {
            int col = colBase + wn * 64 + in * 8 + (lane & 3) * 2;
#pragma unroll
            for (int im = 0; im < 4; im++) {
                int row0 = rowBase + wm * 64 + im * 16 + (lane >> 2);
                f16 h00 = __float2half_rn(acc[im][in][0]);
                f16 h01 = __float2half_rn(acc[im][in][1]);
                f16 h10 = __float2half_rn(acc[im][in][2]);
                f16 h11 = __float2half_rn(acc[im][in][3]);
                *(ushort2*)(C + (size_t)row0 * D_ + col) = make_ushort2(hbits(h00), hbits(h01));
                *(ushort2*)(C + (size_t)(row0 + 8) * D_ + col) = make_ushort2(hbits(h10), hbits(h11));
            }
        }
    }
}

// ---------------- fused softmax + dot: warp per row -----------------------
// rowsum[b,k] = sum_q softmax_q(S[b,k,:]) * (C16[b,k,q] + r2[q])
__global__ void smdot_kernel() {
    const int warp = threadIdx.x >> 5, lane = threadIdx.x & 31;
    const size_t row = (size_t)blockIdx.x * 8 + warp;   // 0..16383
    const int b = (int)(row >> 10), k = (int)(row & 1023);
    const float* __restrict__ Sp = g_S + ((size_t)b * T_ + k) * T_;
    const f16* __restrict__ Cp = g_C16 + ((size_t)b * T_ + k) * T_;

    float4 v[8];
#pragma unroll
    for (int i = 0; i < 8; i++) v[i] = *(const float4*)(Sp + (lane + 32 * i) * 4);
    float m = -3.4e38f;
#pragma unroll
    for (int i = 0; i < 8; i++)
        m = fmaxf(m, fmaxf(fmaxf(v[i].x, v[i].y), fmaxf(v[i].z, v[i].w)));
#pragma unroll
    for (int o = 16; o; o >>= 1) m = fmaxf(m, __shfl_xor_sync(0xffffffffu, m, o));

    float se = 0.f, sc = 0.f;
#pragma unroll
    for (int i = 0; i < 8; i++) {
        int q4 = lane + 32 * i;
        ushort4 cu = ((const ushort4*)Cp)[q4];
        float4 rr = *(const float4*)(g_r2 + q4 * 4);
        f16 c0, c1, c2, c3;
        *reinterpret_cast<unsigned short*>(&c0) = cu.x;
        *reinterpret_cast<unsigned short*>(&c1) = cu.y;
        *reinterpret_cast<unsigned short*>(&c2) = cu.z;
        *reinterpret_cast<unsigned short*>(&c3) = cu.w;
        float e0 = expf(v[i].x - m), e1 = expf(v[i].y - m);
        float e2 = expf(v[i].z - m), e3 = expf(v[i].w - m);
        se += e0 + e1 + e2 + e3;
        sc += e0 * (__half2float(c0) + rr.x) + e1 * (__half2float(c1) + rr.y)
            + e2 * (__half2float(c2) + rr.z) + e3 * (__half2float(c3) + rr.w);
    }
#pragma unroll
    for (int o = 16; o; o >>= 1) {
        se += __shfl_xor_sync(0xffffffffu, se, o);
        sc += __shfl_xor_sync(0xffffffffu, sc, o);
    }
    if (lane == 0) g_rowsum[row] = sc / se;
}

// ---------------- final: out[b] = sum_k rowsum[b,k] + bfc ----------------
__global__ void final_kernel(const float* __restrict__ bfc, float* __restrict__ out) {
    const int b = blockIdx.x;
    const int tid = threadIdx.x;  // 256
    const float* rs = g_rowsum + (size_t)b * T_;
    float v = 0.f;
#pragma unroll
    for (int i = 0; i < 4; i++) v += rs[tid + i * 256];
    __shared__ float red[256];
    red[tid] = v;
    __syncthreads();
#pragma unroll
    for (int s = 128; s > 0; s >>= 1) {
        if (tid < s) red[tid] += red[tid + s];
        __syncthreads();
    }
    if (tid == 0) out[b] = red[0] + bfc[0];
}

// ---------------- launch ----------------
extern "C" void kernel_launch(void* const* d_in, const int* in_sizes, int n_in,
                              void* d_out, int out_size) {
    (void)in_sizes; (void)n_in; (void)out_size;
    const float* x   = (const float*)d_in[0];
    const float* Wq  = (const float*)d_in[1];
    const float* Wk  = (const float*)d_in[3];
    const float* bk  = (const float*)d_in[4];
    const float* Wv  = (const float*)d_in[5];
    const float* bv  = (const float*)d_in[6];
    const float* Wfc = (const float*)d_in[7];
    const float* bfc = (const float*)d_in[8];
    float* out = (float*)d_out;

    cudaFuncSetAttribute(nfold16,   cudaFuncAttributeMaxDynamicSharedMemorySize, DYN);
    cudaFuncSetAttribute(y16_mma,   cudaFuncAttributeMaxDynamicSharedMemorySize, DYN);
    cudaFuncSetAttribute(stc16_mma, cudaFuncAttributeMaxDynamicSharedMemorySize, DYN);

    // OUR index 3 (= ncu capture slot) stays on the Y GEMM.
    split_all<<<(N4_ALL + 255) / 256, 256>>>(x, Wq, Wk, Wv, Wfc);        // 0
    nfold16<<<dim3(8, 4, 2), NT, DYN>>>();                                // 1: N1, N2
    gemv_ur<<<256, 256>>>(Wq, bk, Wfc, bv);                               // 2: u, r2
    y16_mma<<<dim3(8, 64), NT, DYN>>>();                                  // 3: Y <- profiled
    gemv_c<<<B_ * T_ / 8, 256>>>(x);                                      // 4: c
    stc16_mma<<<dim3(8, 4, 32), NT, DYN>>>();                             // 5: S + C
    smdot_kernel<<<(B_ * T_) / 8, 256>>>();                               // 6
    final_kernel<<<B_, 256>>>(bfc, out);                                  // 7
}

// round 16
// speedup vs baseline: 1.0972x; 1.0972x over previous
#include <cuda_runtime.h>
#include <cuda_fp16.h>
#include <cstdint>
#include <math.h>

#define B_ 16
#define T_ 1024
#define D_ 1024
#define TD (T_ * D_)

typedef __half f16;

// ---------------- scratch (device globals; no allocations) ----------------
static __device__ f16  g_X16[B_ * TD];     // fp16(x)
static __device__ f16  g_Wq16[D_ * D_];
static __device__ f16  g_Wk16[D_ * D_];
static __device__ f16  g_Wv16[D_ * D_];
static __device__ f16  g_W216[TD];         // fp16(Wfc) viewed [q, d]
static __device__ f16  g_N116[D_ * D_];    // fp16( (1/32) Wq.Wk^T )
static __device__ f16  g_N216[TD];         // fp16( W2.Wv^T )
static __device__ f16  g_Y16[B_ * TD];     // fp16( X.N1^T )
static __device__ f16  g_C16[B_ * TD];     // fp16( X.N2^T ) per batch
static __device__ float g_S[(size_t)B_ * T_ * T_];
static __device__ float g_u[D_];           // (1/32) Wq.bk
static __device__ float g_c[B_ * T_];      // x_t.u
static __device__ float g_r2[T_];          // bv.W2[q]
static __device__ float g_rowsum[B_ * T_];

// ---------------- low-level helpers ----------------
__device__ __forceinline__ uint32_t smem_u32(const void* p) {
    uint32_t a;
    asm("{ .reg .u64 t; cvta.to.shared.u64 t, %1; cvt.u32.u64 %0, t; }"
        : "=r"(a) : "l"(p));
    return a;
}
__device__ __forceinline__ void cpa16(uint32_t s, const void* g) {
    asm volatile("cp.async.cg.shared.global [%0], [%1], 16;" :: "r"(s), "l"(g));
}
__device__ __forceinline__ void cpa_commit() {
    asm volatile("cp.async.commit_group;" ::: "memory");
}
__device__ __forceinline__ void cpa_wait1() {
    asm volatile("cp.async.wait_group 1;" ::: "memory");
}
__device__ __forceinline__ void cpa_wait0() {
    asm volatile("cp.async.wait_group 0;" ::: "memory");
}
__device__ __forceinline__ void ldsm4(uint32_t (&r)[4], uint32_t addr) {
    asm volatile("ldmatrix.sync.aligned.m8n8.x4.shared.b16 {%0,%1,%2,%3}, [%4];"
        : "=r"(r[0]), "=r"(r[1]), "=r"(r[2]), "=r"(r[3]) : "r"(addr));
}
__device__ __forceinline__ void mma16816h(float* d, const uint32_t* a,
                                          uint32_t b0, uint32_t b1) {
    asm volatile(
        "mma.sync.aligned.m16n8k16.row.col.f32.f16.f16.f32 "
        "{%0,%1,%2,%3}, {%4,%5,%6,%7}, {%8,%9}, {%0,%1,%2,%3};"
        : "+f"(d[0]), "+f"(d[1]), "+f"(d[2]), "+f"(d[3])
        : "r"(a[0]), "r"(a[1]), "r"(a[2]), "r"(a[3]), "r"(b0), "r"(b1));
}
__device__ __forceinline__ unsigned short hbits(f16 h) {
    return *reinterpret_cast<unsigned short*>(&h);
}

// ---------------- merged split kernel: everything -> fp16 -----------------
#define N4_X   (B_ * TD / 4)
#define N4_W   (D_ * D_ / 4)
#define N4_ALL (N4_X + 4 * N4_W)

__global__ void split_all(const float* __restrict__ x, const float* __restrict__ Wq,
                          const float* __restrict__ Wk, const float* __restrict__ Wv,
                          const float* __restrict__ Wfc) {
    int i = blockIdx.x * blockDim.x + threadIdx.x;
    if (i >= N4_ALL) return;
    int j = i;
    const float* src;
    f16* dst;
    if (j < N4_X) { src = x; dst = g_X16; }
    else {
        j -= N4_X;
        if (j < N4_W)          { src = Wq;  dst = g_Wq16; }
        else if (j < 2 * N4_W) { j -= N4_W;     src = Wk;  dst = g_Wk16; }
        else if (j < 3 * N4_W) { j -= 2 * N4_W; src = Wv;  dst = g_Wv16; }
        else                   { j -= 3 * N4_W; src = Wfc; dst = g_W216; }
    }
    float4 v = ((const float4*)src)[j];
    f16 h0 = __float2half_rn(v.x), h1 = __float2half_rn(v.y);
    f16 h2 = __float2half_rn(v.z), h3 = __float2half_rn(v.w);
    ((ushort4*)dst)[j] = make_ushort4(hbits(h0), hbits(h1), hbits(h2), hbits(h3));
}

// ---------------- GEMV kernels (warp per row, fp32) ----------------
__global__ void gemv_ur(const float* __restrict__ Wq, const float* __restrict__ bk,
                        const float* __restrict__ Wfc, const float* __restrict__ bv) {
    int warp = threadIdx.x >> 5, lane = threadIdx.x & 31;
    const float *mat, *vec;
    float* dst;
    float scale;
    int row;
    if (blockIdx.x < 128) { mat = Wq;  vec = bk; dst = g_u;  scale = 0.03125f; row = blockIdx.x * 8 + warp; }
    else                  { mat = Wfc; vec = bv; dst = g_r2; scale = 1.0f;     row = (blockIdx.x - 128) * 8 + warp; }
    const float4* w4 = (const float4*)(mat + (size_t)row * D_);
    const float4* b4 = (const float4*)vec;
    float s = 0.f;
#pragma unroll
    for (int i = 0; i < 8; i++) {
        float4 w = w4[lane + i * 32], b = b4[lane + i * 32];
        s += w.x * b.x + w.y * b.y + w.z * b.z + w.w * b.w;
    }
#pragma unroll
    for (int o = 16; o; o >>= 1) s += __shfl_xor_sync(0xffffffffu, s, o);
    if (lane == 0) dst[row] = s * scale;
}

__global__ void gemv_c(const float* __restrict__ x) {
    int warp = threadIdx.x >> 5, lane = threadIdx.x & 31;
    int row = blockIdx.x * 8 + warp;   // 0..16383
    const float4* x4 = (const float4*)(x + (size_t)row * D_);
    const float4* u4 = (const float4*)g_u;
    float s = 0.f;
#pragma unroll
    for (int i = 0; i < 8; i++) {
        float4 w = x4[lane + i * 32], b = u4[lane + i * 32];
        s += w.x * b.x + w.y * b.y + w.z * b.z + w.w * b.w;
    }
#pragma unroll
    for (int o = 16; o; o >>= 1) s += __shfl_xor_sync(0xffffffffu, s, o);
    if (lane == 0) g_c[row] = s;
}

// ===================== fp16 mainloop: CTA 128x128, 4 warps (2x2) ==========
// Warp tile 64x64, ktile 64 (4 x k16), 2-stage cp.async, occ 2 (8 warps/SM).
// kk-level FRAGMENT double buffering: all 8 fragments for kk+1 are loaded
// before kk's 32 MMAs issue -> exposed LDS latency once per ktile, not 4x.
// Correct double-barrier ordering.
#define NTHR16 128
#define LDB16 144            // 128B row + 16B pad -> conflict-free ldmatrix
#define OPB16 (128 * LDB16)  // 18432
#define STG16 (2 * OPB16)    // 36864 per stage (A+B)
#define DYN16 (2 * STG16)    // 73728 -> 2 CTAs/SM

__device__ __forceinline__ void load_stage16(uint32_t sb,
        const f16* __restrict__ A, const f16* __restrict__ Bm,
        int rowBase, int colBase, int kt, int tid) {
#pragma unroll
    for (int op = 0; op < 2; op++) {
        const f16* s = op ? Bm : A;
        int rb = op ? colBase : rowBase;
#pragma unroll
        for (int i = 0; i < 8; i++) {
            int chunk = tid + i * NTHR16;   // 0..1023
            int row = chunk >> 3, c = chunk & 7;
            cpa16(sb + op * OPB16 + row * LDB16 + c * 16,
                  s + (size_t)(rb + row) * D_ + kt * 64 + c * 8);
        }
    }
}

// acc[im 0..3][in 0..7][4]
__device__ __forceinline__ void gemm16_ml(uint32_t sbase,
        const f16* __restrict__ A, const f16* __restrict__ Bm,
        int rowBase, int colBase, int tid, float acc[4][8][4]) {
    const int lane = tid & 31, wid = tid >> 5;
    const int wm = wid & 1, wn = wid >> 1;     // 2x2 warps
    const int lrow = lane & 15;
    const int lcol = (lane >> 4) * 16;

#pragma unroll
    for (int im = 0; im < 4; im++)
#pragma unroll
        for (int in = 0; in < 8; in++)
#pragma unroll
            for (int j = 0; j < 4; j++) acc[im][in][j] = 0.f;

    load_stage16(sbase, A, Bm, rowBase, colBase, 0, tid);
    cpa_commit();

    for (int kt = 0; kt < 16; kt++) {       // 16 ktiles of 64
        if (kt + 1 < 16) {
            load_stage16(sbase + ((kt + 1) & 1) * STG16, A, Bm,
                         rowBase, colBase, kt + 1, tid);
            cpa_commit();
            cpa_wait1();
        } else {
            cpa_wait0();
        }
        __syncthreads();          // publish stage kt

        uint32_t st = sbase + (kt & 1) * STG16;
        uint32_t aA = st + (wm * 64 + lrow) * LDB16 + lcol;
        uint32_t aB = st + OPB16 + (wn * 64 + lrow) * LDB16 + lcol;

        uint32_t af[2][4][4], bf[2][4][4];   // fragment double buffer
        // load kk=0 fragments
#pragma unroll
        for (int im = 0; im < 4; im++) ldsm4(af[0][im], aA + im * 16 * LDB16);
#pragma unroll
        for (int g = 0; g < 4; g++)   ldsm4(bf[0][g], aB + g * 16 * LDB16);

#pragma unroll
        for (int kk = 0; kk < 4; kk++) {
            const int cur = kk & 1, nxt = cur ^ 1;
            if (kk < 3) {   // preload kk+1's 8 fragments behind kk's 32 MMAs
#pragma unroll
                for (int im = 0; im < 4; im++)
                    ldsm4(af[nxt][im], aA + im * 16 * LDB16 + (kk + 1) * 32);
#pragma unroll
                for (int g = 0; g < 4; g++)
                    ldsm4(bf[nxt][g], aB + g * 16 * LDB16 + (kk + 1) * 32);
            }
#pragma unroll
            for (int im = 0; im < 4; im++)
#pragma unroll
                for (int g = 0; g < 4; g++) {
                    mma16816h(acc[im][g * 2 + 0], af[cur][im], bf[cur][g][0], bf[cur][g][2]);
                    mma16816h(acc[im][g * 2 + 1], af[cur][im], bf[cur][g][1], bf[cur][g][3]);
                }
        }
        __syncthreads();          // WAR: stage free
    }
}

// ---------------- N folds (fp16): grid (8,8,2) ----------------
// z=0: N116 = fp16((1/32) Wq.Wk^T) ; z=1: N216 = fp16(W2.Wv^T)
__global__ void __launch_bounds__(NTHR16, 2)
nfold16() {
    extern __shared__ char dyn[];
    uint32_t sbase = smem_u32(dyn);
    const int tid = threadIdx.x;
    const int lane = tid & 31, wid = tid >> 5;
    const int wm = wid & 1, wn = wid >> 1;
    const int rowBase = blockIdx.y * 128, colBase = blockIdx.x * 128;

    const f16 *A, *Bm;
    f16* O;
    float scale;
    if (blockIdx.z == 0) { A = g_Wq16; Bm = g_Wk16; O = g_N116; scale = 0.03125f; }
    else                 { A = g_W216; Bm = g_Wv16; O = g_N216; scale = 1.0f; }

    float acc[4][8][4];
    gemm16_ml(sbase, A, Bm, rowBase, colBase, tid, acc);

#pragma unroll
    for (int in = 0; in < 8; in++) {
        int col = colBase + wn * 64 + in * 8 + (lane & 3) * 2;
#pragma unroll
        for (int im = 0; im < 4; im++) {
            int row0 = rowBase + wm * 64 + im * 16 + (lane >> 2);
            f16 h00 = __float2half_rn(acc[im][in][0] * scale);
            f16 h01 = __float2half_rn(acc[im][in][1] * scale);
            f16 h10 = __float2half_rn(acc[im][in][2] * scale);
            f16 h11 = __float2half_rn(acc[im][in][3] * scale);
            *(ushort2*)(O + (size_t)row0 * D_ + col) = make_ushort2(hbits(h00), hbits(h01));
            *(ushort2*)(O + (size_t)(row0 + 8) * D_ + col) = make_ushort2(hbits(h10), hbits(h11));
        }
    }
}

// ---------------- Y = fp16( X16 . N116^T ) : grid (8,128) ----------------
__global__ void __launch_bounds__(NTHR16, 2)
y16_mma() {
    extern __shared__ char dyn[];
    uint32_t sbase = smem_u32(dyn);
    const int tid = threadIdx.x;
    const int lane = tid & 31, wid = tid >> 5;
    const int wm = wid & 1, wn = wid >> 1;
    const int rowBase = blockIdx.y * 128, colBase = blockIdx.x * 128;

    float acc[4][8][4];
    gemm16_ml(sbase, g_X16, g_N116, rowBase, colBase, tid, acc);

#pragma unroll
    for (int in = 0; in < 8; in++) {
        int col = colBase + wn * 64 + in * 8 + (lane & 3) * 2;
#pragma unroll
        for (int im = 0; im < 4; im++) {
            int row0 = rowBase + wm * 64 + im * 16 + (lane >> 2);
            f16 h00 = __float2half_rn(acc[im][in][0]);
            f16 h01 = __float2half_rn(acc[im][in][1]);
            f16 h10 = __float2half_rn(acc[im][in][2]);
            f16 h11 = __float2half_rn(acc[im][in][3]);
            *(ushort2*)(g_Y16 + (size_t)row0 * D_ + col) = make_ushort2(hbits(h00), hbits(h01));
            *(ushort2*)(g_Y16 + (size_t)(row0 + 8) * D_ + col) = make_ushort2(hbits(h10), hbits(h11));
        }
    }
}

// ---------------- S + C merged: grid (8, 8, 32) ----------------
// z = b + 16*job. job0: S[b][k][q] = Y16_b[k].X16_b[q] + c_b[q]  (fp32)
//                 job1: C16[b][k][q] = X16_b[k].N216[q]          (fp16)
__global__ void __launch_bounds__(NTHR16, 2)
stc16_mma() {
    extern __shared__ char dyn[];
    uint32_t sbase = smem_u32(dyn);
    const int tid = threadIdx.x;
    const int lane = tid & 31, wid = tid >> 5;
    const int wm = wid & 1, wn = wid >> 1;
    const int b = blockIdx.z & 15;
    const int job = blockIdx.z >> 4;
    const int rowBase = blockIdx.y * 128, colBase = blockIdx.x * 128;

    const f16* A = job ? (g_X16 + (size_t)b * TD) : (g_Y16 + (size_t)b * TD);
    const f16* Bm = job ? g_N216 : (g_X16 + (size_t)b * TD);

    float acc[4][8][4];
    gemm16_ml(sbase, A, Bm, rowBase, colBase, tid, acc);

    if (job == 0) {
        float* __restrict__ S = g_S + (size_t)b * T_ * T_;
        const float* __restrict__ c = g_c + (size_t)b * T_;
#pragma unroll
        for (int in = 0; in < 8; in++) {
            int col = colBase + wn * 64 + in * 8 + (lane & 3) * 2;
            float2 cc = *(const float2*)(c + col);
#pragma unroll
            for (int im = 0; im < 4; im++) {
                int row0 = rowBase + wm * 64 + im * 16 + (lane >> 2);
                *(float2*)(S + (size_t)row0 * T_ + col) =
                    make_float2(acc[im][in][0] + cc.x, acc[im][in][1] + cc.y);
                *(float2*)(S + (size_t)(row0 + 8) * T_ + col) =
                    make_float2(acc[im][in][2] + cc.x, acc[im][in][3] + cc.y);
            }
        }
    } else {
        f16* __restrict__ C = g_C16 + (size_t)b * TD;
#pragma unroll
        for (int in = 0; in < 8; in++) {
            int col = colBase + wn * 64 + in * 8 + (lane & 3) * 2;
#pragma unroll
            for (int im = 0; im < 4; im++) {
                int row0 = rowBase + wm * 64 + im * 16 + (lane >> 2);
                f16 h00 = __float2half_rn(acc[im][in][0]);
                f16 h01 = __float2half_rn(acc[im][in][1]);
                f16 h10 = __float2half_rn(acc[im][in][2]);
                f16 h11 = __float2half_rn(acc[im][in][3]);
                *(ushort2*)(C + (size_t)row0 * D_ + col) = make_ushort2(hbits(h00), hbits(h01));
                *(ushort2*)(C + (size_t)(row0 + 8) * D_ + col) = make_ushort2(hbits(h10), hbits(h11));
            }
        }
    }
}

// ---------------- fused softmax + dot: warp per row -----------------------
// rowsum[b,k] = sum_q softmax_q(S[b,k,:]) * (C16[b,k,q] + r2[q])
__global__ void smdot_kernel() {
    const int warp = threadIdx.x >> 5, lane = threadIdx.x & 31;
    const size_t row = (size_t)blockIdx.x * 8 + warp;   // 0..16383
    const int b = (int)(row >> 10), k = (int)(row & 1023);
    const float* __restrict__ Sp = g_S + ((size_t)b * T_ + k) * T_;
    const f16* __restrict__ Cp = g_C16 + ((size_t)b * T_ + k) * T_;

    float4 v[8];
#pragma unroll
    for (int i = 0; i < 8; i++) v[i] = *(const float4*)(Sp + (lane + 32 * i) * 4);
    float m = -3.4e38f;
#pragma unroll
    for (int i = 0; i < 8; i++)
        m = fmaxf(m, fmaxf(fmaxf(v[i].x, v[i].y), fmaxf(v[i].z, v[i].w)));
#pragma unroll
    for (int o = 16; o; o >>= 1) m = fmaxf(m, __shfl_xor_sync(0xffffffffu, m, o));

    float se = 0.f, sc = 0.f;
#pragma unroll
    for (int i = 0; i < 8; i++) {
        int q4 = lane + 32 * i;
        ushort4 cu = ((const ushort4*)Cp)[q4];
        float4 rr = *(const float4*)(g_r2 + q4 * 4);
        f16 c0, c1, c2, c3;
        *reinterpret_cast<unsigned short*>(&c0) = cu.x;
        *reinterpret_cast<unsigned short*>(&c1) = cu.y;
        *reinterpret_cast<unsigned short*>(&c2) = cu.z;
        *reinterpret_cast<unsigned short*>(&c3) = cu.w;
        float e0 = expf(v[i].x - m), e1 = expf(v[i].y - m);
        float e2 = expf(v[i].z - m), e3 = expf(v[i].w - m);
        se += e0 + e1 + e2 + e3;
        sc += e0 * (__half2float(c0) + rr.x) + e1 * (__half2float(c1) + rr.y)
            + e2 * (__half2float(c2) + rr.z) + e3 * (__half2float(c3) + rr.w);
    }
#pragma unroll
    for (int o = 16; o; o >>= 1) {
        se += __shfl_xor_sync(0xffffffffu, se, o);
        sc += __shfl_xor_sync(0xffffffffu, sc, o);
    }
    if (lane == 0) g_rowsum[row] = sc / se;
}

// ---------------- final: out[b] = sum_k rowsum[b,k] + bfc ----------------
__global__ void final_kernel(const float* __restrict__ bfc, float* __restrict__ out) {
    const int b = blockIdx.x;
    const int tid = threadIdx.x;  // 256
    const float* rs = g_rowsum + (size_t)b * T_;
    float v = 0.f;
#pragma unroll
    for (int i = 0; i < 4; i++) v += rs[tid + i * 256];
    __shared__ float red[256];
    red[tid] = v;
    __syncthreads();
#pragma unroll
    for (int s = 128; s > 0; s >>= 1) {
        if (tid < s) red[tid] += red[tid + s];
        __syncthreads();
    }
    if (tid == 0) out[b] = red[0] + bfc[0];
}

// ---------------- launch ----------------
extern "C" void kernel_launch(void* const* d_in, const int* in_sizes, int n_in,
                              void* d_out, int out_size) {
    (void)in_sizes; (void)n_in; (void)out_size;
    const float* x   = (const float*)d_in[0];
    const float* Wq  = (const float*)d_in[1];
    const float* Wk  = (const float*)d_in[3];
    const float* bk  = (const float*)d_in[4];
    const float* Wv  = (const float*)d_in[5];
    const float* bv  = (const float*)d_in[6];
    const float* Wfc = (const float*)d_in[7];
    const float* bfc = (const float*)d_in[8];
    float* out = (float*)d_out;

    cudaFuncSetAttribute(nfold16,   cudaFuncAttributeMaxDynamicSharedMemorySize, DYN16);
    cudaFuncSetAttribute(y16_mma,   cudaFuncAttributeMaxDynamicSharedMemorySize, DYN16);
    cudaFuncSetAttribute(stc16_mma, cudaFuncAttributeMaxDynamicSharedMemorySize, DYN16);

    // OUR index 3 (= ncu capture slot) stays on the Y GEMM.
    split_all<<<(N4_ALL + 255) / 256, 256>>>(x, Wq, Wk, Wv, Wfc);        // 0
    nfold16<<<dim3(8, 8, 2), NTHR16, DYN16>>>();                          // 1: N1, N2
    gemv_ur<<<256, 256>>>(Wq, bk, Wfc, bv);                               // 2: u, r2
    y16_mma<<<dim3(8, 128), NTHR16, DYN16>>>();                           // 3: Y <- profiled
    gemv_c<<<B_ * T_ / 8, 256>>>(x);                                      // 4: c
    stc16_mma<<<dim3(8, 8, 32), NTHR16, DYN16>>>();                       // 5: S + C
    smdot_kernel<<<(B_ * T_) / 8, 256>>>();                               // 6
    final_kernel<<<B_, 256>>>(bfc, out);                                  // 7
}

// round 17
// speedup vs baseline: 1.1065x; 1.0084x over previous
#include <cuda_runtime.h>
#include <cuda_fp16.h>
#include <cstdint>
#include <math.h>

#define B_ 16
#define T_ 1024
#define D_ 1024
#define TD (T_ * D_)

typedef __half f16;

// ---------------- scratch (device globals; no allocations) ----------------
static __device__ f16  g_X16[B_ * TD];     // fp16(x)
static __device__ f16  g_Wq16[D_ * D_];
static __device__ f16  g_Wk16[D_ * D_];
static __device__ f16  g_Wv16[D_ * D_];
static __device__ f16  g_W216[TD];         // fp16(Wfc) viewed [q, d]
static __device__ f16  g_N116[D_ * D_];    // fp16( (1/32) Wq.Wk^T )
static __device__ f16  g_N216[TD];         // fp16( W2.Wv^T )
static __device__ f16  g_Y16[B_ * TD];     // fp16( X.N1^T )
static __device__ f16  g_C16[B_ * TD];     // fp16( X.N2^T )
static __device__ f16  g_S16[(size_t)B_ * T_ * T_];  // fp16 scores (+c)
static __device__ float g_u[D_];           // (1/32) Wq.bk
static __device__ float g_c[B_ * T_];      // x_t.u
static __device__ float g_r2[T_];          // bv.W2[q]
static __device__ float g_rowsum[B_ * T_];

// ---------------- low-level helpers ----------------
__device__ __forceinline__ uint32_t smem_u32(const void* p) {
    uint32_t a;
    asm("{ .reg .u64 t; cvta.to.shared.u64 t, %1; cvt.u32.u64 %0, t; }"
        : "=r"(a) : "l"(p));
    return a;
}
__device__ __forceinline__ void cpa16(uint32_t s, const void* g) {
    asm volatile("cp.async.cg.shared.global [%0], [%1], 16;" :: "r"(s), "l"(g));
}
__device__ __forceinline__ void cpa_commit() {
    asm volatile("cp.async.commit_group;" ::: "memory");
}
__device__ __forceinline__ void cpa_wait1() {
    asm volatile("cp.async.wait_group 1;" ::: "memory");
}
__device__ __forceinline__ void cpa_wait0() {
    asm volatile("cp.async.wait_group 0;" ::: "memory");
}
__device__ __forceinline__ void ldsm4(uint32_t (&r)[4], uint32_t addr) {
    asm volatile("ldmatrix.sync.aligned.m8n8.x4.shared.b16 {%0,%1,%2,%3}, [%4];"
        : "=r"(r[0]), "=r"(r[1]), "=r"(r[2]), "=r"(r[3]) : "r"(addr));
}
__device__ __forceinline__ void mma16816h(float* d, const uint32_t* a,
                                          uint32_t b0, uint32_t b1) {
    asm volatile(
        "mma.sync.aligned.m16n8k16.row.col.f32.f16.f16.f32 "
        "{%0,%1,%2,%3}, {%4,%5,%6,%7}, {%8,%9}, {%0,%1,%2,%3};"
        : "+f"(d[0]), "+f"(d[1]), "+f"(d[2]), "+f"(d[3])
        : "r"(a[0]), "r"(a[1]), "r"(a[2]), "r"(a[3]), "r"(b0), "r"(b1));
}
__device__ __forceinline__ unsigned short hbits(f16 h) {
    return *reinterpret_cast<unsigned short*>(&h);
}

// ---------------- merged split kernel: everything -> fp16 -----------------
#define N4_X   (B_ * TD / 4)
#define N4_W   (D_ * D_ / 4)
#define N4_ALL (N4_X + 4 * N4_W)

__global__ void split_all(const float* __restrict__ x, const float* __restrict__ Wq,
                          const float* __restrict__ Wk, const float* __restrict__ Wv,
                          const float* __restrict__ Wfc) {
    int i = blockIdx.x * blockDim.x + threadIdx.x;
    if (i >= N4_ALL) return;
    int j = i;
    const float* src;
    f16* dst;
    if (j < N4_X) { src = x; dst = g_X16; }
    else {
        j -= N4_X;
        if (j < N4_W)          { src = Wq;  dst = g_Wq16; }
        else if (j < 2 * N4_W) { j -= N4_W;     src = Wk;  dst = g_Wk16; }
        else if (j < 3 * N4_W) { j -= 2 * N4_W; src = Wv;  dst = g_Wv16; }
        else                   { j -= 3 * N4_W; src = Wfc; dst = g_W216; }
    }
    float4 v = ((const float4*)src)[j];
    f16 h0 = __float2half_rn(v.x), h1 = __float2half_rn(v.y);
    f16 h2 = __float2half_rn(v.z), h3 = __float2half_rn(v.w);
    ((ushort4*)dst)[j] = make_ushort4(hbits(h0), hbits(h1), hbits(h2), hbits(h3));
}

// ---------------- GEMV kernels (warp per row, fp32) ----------------
__global__ void gemv_ur(const float* __restrict__ Wq, const float* __restrict__ bk,
                        const float* __restrict__ Wfc, const float* __restrict__ bv) {
    int warp = threadIdx.x >> 5, lane = threadIdx.x & 31;
    const float *mat, *vec;
    float* dst;
    float scale;
    int row;
    if (blockIdx.x < 128) { mat = Wq;  vec = bk; dst = g_u;  scale = 0.03125f; row = blockIdx.x * 8 + warp; }
    else                  { mat = Wfc; vec = bv; dst = g_r2; scale = 1.0f;     row = (blockIdx.x - 128) * 8 + warp; }
    const float4* w4 = (const float4*)(mat + (size_t)row * D_);
    const float4* b4 = (const float4*)vec;
    float s = 0.f;
#pragma unroll
    for (int i = 0; i < 8; i++) {
        float4 w = w4[lane + i * 32], b = b4[lane + i * 32];
        s += w.x * b.x + w.y * b.y + w.z * b.z + w.w * b.w;
    }
#pragma unroll
    for (int o = 16; o; o >>= 1) s += __shfl_xor_sync(0xffffffffu, s, o);
    if (lane == 0) dst[row] = s * scale;
}

__global__ void gemv_c(const float* __restrict__ x) {
    int warp = threadIdx.x >> 5, lane = threadIdx.x & 31;
    int row = blockIdx.x * 8 + warp;   // 0..16383
    const float4* x4 = (const float4*)(x + (size_t)row * D_);
    const float4* u4 = (const float4*)g_u;
    float s = 0.f;
#pragma unroll
    for (int i = 0; i < 8; i++) {
        float4 w = x4[lane + i * 32], b = u4[lane + i * 32];
        s += w.x * b.x + w.y * b.y + w.z * b.z + w.w * b.w;
    }
#pragma unroll
    for (int o = 16; o; o >>= 1) s += __shfl_xor_sync(0xffffffffu, s, o);
    if (lane == 0) g_c[row] = s;
}

// ===================== fp16 mainloop: CTA 128x128, 4 warps (2x2) ==========
// Warp tile 64x64, ktile 64 (4 x k16), 2-stage cp.async, occ 2 (8 warps/SM).
// kk-level fragment double buffering; correct double-barrier ordering.
// At the legacy-HMMA (f32-acc, half-rate) hardware ceiling -- do not touch.
#define NTHR16 128
#define LDB16 144            // 128B row + 16B pad -> conflict-free ldmatrix
#define OPB16 (128 * LDB16)  // 18432
#define STG16 (2 * OPB16)    // 36864 per stage (A+B)
#define DYN16 (2 * STG16)    // 73728 -> 2 CTAs/SM

__device__ __forceinline__ void load_stage16(uint32_t sb,
        const f16* __restrict__ A, const f16* __restrict__ Bm,
        int rowBase, int colBase, int kt, int tid) {
#pragma unroll
    for (int op = 0; op < 2; op++) {
        const f16* s = op ? Bm : A;
        int rb = op ? colBase : rowBase;
#pragma unroll
        for (int i = 0; i < 8; i++) {
            int chunk = tid + i * NTHR16;   // 0..1023
            int row = chunk >> 3, c = chunk & 7;
            cpa16(sb + op * OPB16 + row * LDB16 + c * 16,
                  s + (size_t)(rb + row) * D_ + kt * 64 + c * 8);
        }
    }
}

// acc[im 0..3][in 0..7][4]
__device__ __forceinline__ void gemm16_ml(uint32_t sbase,
        const f16* __restrict__ A, const f16* __restrict__ Bm,
        int rowBase, int colBase, int tid, float acc[4][8][4]) {
    const int lane = tid & 31, wid = tid >> 5;
    const int wm = wid & 1, wn = wid >> 1;     // 2x2 warps
    const int lrow = lane & 15;
    const int lcol = (lane >> 4) * 16;

#pragma unroll
    for (int im = 0; im < 4; im++)
#pragma unroll
        for (int in = 0; in < 8; in++)
#pragma unroll
            for (int j = 0; j < 4; j++) acc[im][in][j] = 0.f;

    load_stage16(sbase, A, Bm, rowBase, colBase, 0, tid);
    cpa_commit();

    for (int kt = 0; kt < 16; kt++) {       // 16 ktiles of 64
        if (kt + 1 < 16) {
            load_stage16(sbase + ((kt + 1) & 1) * STG16, A, Bm,
                         rowBase, colBase, kt + 1, tid);
            cpa_commit();
            cpa_wait1();
        } else {
            cpa_wait0();
        }
        __syncthreads();          // publish stage kt

        uint32_t st = sbase + (kt & 1) * STG16;
        uint32_t aA = st + (wm * 64 + lrow) * LDB16 + lcol;
        uint32_t aB = st + OPB16 + (wn * 64 + lrow) * LDB16 + lcol;

        uint32_t af[2][4][4], bf[2][4][4];   // fragment double buffer
#pragma unroll
        for (int im = 0; im < 4; im++) ldsm4(af[0][im], aA + im * 16 * LDB16);
#pragma unroll
        for (int g = 0; g < 4; g++)   ldsm4(bf[0][g], aB + g * 16 * LDB16);

#pragma unroll
        for (int kk = 0; kk < 4; kk++) {
            const int cur = kk & 1, nxt = cur ^ 1;
            if (kk < 3) {
#pragma unroll
                for (int im = 0; im < 4; im++)
                    ldsm4(af[nxt][im], aA + im * 16 * LDB16 + (kk + 1) * 32);
#pragma unroll
                for (int g = 0; g < 4; g++)
                    ldsm4(bf[nxt][g], aB + g * 16 * LDB16 + (kk + 1) * 32);
            }
#pragma unroll
            for (int im = 0; im < 4; im++)
#pragma unroll
                for (int g = 0; g < 4; g++) {
                    mma16816h(acc[im][g * 2 + 0], af[cur][im], bf[cur][g][0], bf[cur][g][2]);
                    mma16816h(acc[im][g * 2 + 1], af[cur][im], bf[cur][g][1], bf[cur][g][3]);
                }
        }
        __syncthreads();          // WAR: stage free
    }
}

// generic fp16-output epilogue
__device__ __forceinline__ void store_f16_tile(f16* __restrict__ O, float acc[4][8][4],
        int rowBase, int colBase, int lane, int wm, int wn, float scale) {
#pragma unroll
    for (int in = 0; in < 8; in++) {
        int col = colBase + wn * 64 + in * 8 + (lane & 3) * 2;
#pragma unroll
        for (int im = 0; im < 4; im++) {
            int row0 = rowBase + wm * 64 + im * 16 + (lane >> 2);
            f16 h00 = __float2half_rn(acc[im][in][0] * scale);
            f16 h01 = __float2half_rn(acc[im][in][1] * scale);
            f16 h10 = __float2half_rn(acc[im][in][2] * scale);
            f16 h11 = __float2half_rn(acc[im][in][3] * scale);
            *(ushort2*)(O + (size_t)row0 * D_ + col) = make_ushort2(hbits(h00), hbits(h01));
            *(ushort2*)(O + (size_t)(row0 + 8) * D_ + col) = make_ushort2(hbits(h10), hbits(h11));
        }
    }
}

// ---------------- N folds (fp16): grid (8,8,2) ----------------
__global__ void __launch_bounds__(NTHR16, 2)
nfold16() {
    extern __shared__ char dyn[];
    uint32_t sbase = smem_u32(dyn);
    const int tid = threadIdx.x;
    const int lane = tid & 31, wid = tid >> 5;
    const int wm = wid & 1, wn = wid >> 1;
    const int rowBase = blockIdx.y * 128, colBase = blockIdx.x * 128;

    const f16 *A, *Bm;
    f16* O;
    float scale;
    if (blockIdx.z == 0) { A = g_Wq16; Bm = g_Wk16; O = g_N116; scale = 0.03125f; }
    else                 { A = g_W216; Bm = g_Wv16; O = g_N216; scale = 1.0f; }

    float acc[4][8][4];
    gemm16_ml(sbase, A, Bm, rowBase, colBase, tid, acc);
    store_f16_tile(O, acc, rowBase, colBase, lane, wm, wn, scale);
}

// ---------------- Y + C merged: grid (8,128,2) ----------------
// z=0: Y16 = X16 . N116^T ; z=1: C16 = X16 . N216^T  (both [16384 x 1024])
__global__ void __launch_bounds__(NTHR16, 2)
yc16_mma() {
    extern __shared__ char dyn[];
    uint32_t sbase = smem_u32(dyn);
    const int tid = threadIdx.x;
    const int lane = tid & 31, wid = tid >> 5;
    const int wm = wid & 1, wn = wid >> 1;
    const int rowBase = blockIdx.y * 128, colBase = blockIdx.x * 128;

    const f16* Bm = blockIdx.z ? g_N216 : g_N116;
    f16* O = blockIdx.z ? g_C16 : g_Y16;

    float acc[4][8][4];
    gemm16_ml(sbase, g_X16, Bm, rowBase, colBase, tid, acc);
    store_f16_tile(O, acc, rowBase, colBase, lane, wm, wn, 1.0f);
}

// ---------------- S: grid (8,8,16) ----------------
// S16[b][k][q] = fp16( Y16_b[k].X16_b[q] + c_b[q] )
__global__ void __launch_bounds__(NTHR16, 2)
s16_mma() {
    extern __shared__ char dyn[];
    uint32_t sbase = smem_u32(dyn);
    const int tid = threadIdx.x;
    const int lane = tid & 31, wid = tid >> 5;
    const int wm = wid & 1, wn = wid >> 1;
    const int b = blockIdx.z;
    const int rowBase = blockIdx.y * 128, colBase = blockIdx.x * 128;

    float acc[4][8][4];
    gemm16_ml(sbase, g_Y16 + (size_t)b * TD, g_X16 + (size_t)b * TD,
              rowBase, colBase, tid, acc);

    f16* __restrict__ S = g_S16 + (size_t)b * T_ * T_;
    const float* __restrict__ c = g_c + (size_t)b * T_;
#pragma unroll
    for (int in = 0; in < 8; in++) {
        int col = colBase + wn * 64 + in * 8 + (lane & 3) * 2;
        float2 cc = *(const float2*)(c + col);
#pragma unroll
        for (int im = 0; im < 4; im++) {
            int row0 = rowBase + wm * 64 + im * 16 + (lane >> 2);
            f16 h00 = __float2half_rn(acc[im][in][0] + cc.x);
            f16 h01 = __float2half_rn(acc[im][in][1] + cc.y);
            f16 h10 = __float2half_rn(acc[im][in][2] + cc.x);
            f16 h11 = __float2half_rn(acc[im][in][3] + cc.y);
            *(ushort2*)(S + (size_t)row0 * T_ + col) = make_ushort2(hbits(h00), hbits(h01));
            *(ushort2*)(S + (size_t)(row0 + 8) * T_ + col) = make_ushort2(hbits(h10), hbits(h11));
        }
    }
}

// ---------------- fused softmax + dot: warp per row -----------------------
// rowsum[b,k] = sum_q softmax_q(S16[b,k,:]) * (C16[b,k,q] + r2[q])
__global__ void smdot_kernel() {
    const int warp = threadIdx.x >> 5, lane = threadIdx.x & 31;
    const size_t row = (size_t)blockIdx.x * 8 + warp;   // 0..16383
    const int b = (int)(row >> 10), k = (int)(row & 1023);
    const f16* __restrict__ Sp = g_S16 + ((size_t)b * T_ + k) * T_;
    const f16* __restrict__ Cp = g_C16 + ((size_t)b * T_ + k) * T_;

    float v[32];
#pragma unroll
    for (int i = 0; i < 8; i++) {
        ushort4 su = ((const ushort4*)Sp)[lane + 32 * i];
        f16 s0, s1, s2, s3;
        *reinterpret_cast<unsigned short*>(&s0) = su.x;
        *reinterpret_cast<unsigned short*>(&s1) = su.y;
        *reinterpret_cast<unsigned short*>(&s2) = su.z;
        *reinterpret_cast<unsigned short*>(&s3) = su.w;
        v[i * 4 + 0] = __half2float(s0); v[i * 4 + 1] = __half2float(s1);
        v[i * 4 + 2] = __half2float(s2); v[i * 4 + 3] = __half2float(s3);
    }
    float m = -3.4e38f;
#pragma unroll
    for (int i = 0; i < 32; i++) m = fmaxf(m, v[i]);
#pragma unroll
    for (int o = 16; o; o >>= 1) m = fmaxf(m, __shfl_xor_sync(0xffffffffu, m, o));

    float se = 0.f, sc = 0.f;
#pragma unroll
    for (int i = 0; i < 8; i++) {
        int q4 = lane + 32 * i;
        ushort4 cu = ((const ushort4*)Cp)[q4];
        float4 rr = *(const float4*)(g_r2 + q4 * 4);
        f16 c0, c1, c2, c3;
        *reinterpret_cast<unsigned short*>(&c0) = cu.x;
        *reinterpret_cast<unsigned short*>(&c1) = cu.y;
        *reinterpret_cast<unsigned short*>(&c2) = cu.z;
        *reinterpret_cast<unsigned short*>(&c3) = cu.w;
        float e0 = expf(v[i * 4 + 0] - m), e1 = expf(v[i * 4 + 1] - m);
        float e2 = expf(v[i * 4 + 2] - m), e3 = expf(v[i * 4 + 3] - m);
        se += e0 + e1 + e2 + e3;
        sc += e0 * (__half2float(c0) + rr.x) + e1 * (__half2float(c1) + rr.y)
            + e2 * (__half2float(c2) + rr.z) + e3 * (__half2float(c3) + rr.w);
    }
#pragma unroll
    for (int o = 16; o; o >>= 1) {
        se += __shfl_xor_sync(0xffffffffu, se, o);
        sc += __shfl_xor_sync(0xffffffffu, sc, o);
    }
    if (lane == 0) g_rowsum[row] = sc / se;
}

// ---------------- final: out[b] = sum_k rowsum[b,k] + bfc ----------------
__global__ void final_kernel(const float* __restrict__ bfc, float* __restrict__ out) {
    const int b = blockIdx.x;
    const int tid = threadIdx.x;  // 256
    const float* rs = g_rowsum + (size_t)b * T_;
    float v = 0.f;
#pragma unroll
    for (int i = 0; i < 4; i++) v += rs[tid + i * 256];
    __shared__ float red[256];
    red[tid] = v;
    __syncthreads();
#pragma unroll
    for (int s = 128; s > 0; s >>= 1) {
        if (tid < s) red[tid] += red[tid + s];
        __syncthreads();
    }
    if (tid == 0) out[b] = red[0] + bfc[0];
}

// ---------------- launch ----------------
extern "C" void kernel_launch(void* const* d_in, const int* in_sizes, int n_in,
                              void* d_out, int out_size) {
    (void)in_sizes; (void)n_in; (void)out_size;
    const float* x   = (const float*)d_in[0];
    const float* Wq  = (const float*)d_in[1];
    const float* Wk  = (const float*)d_in[3];
    const float* bk  = (const float*)d_in[4];
    const float* Wv  = (const float*)d_in[5];
    const float* bv  = (const float*)d_in[6];
    const float* Wfc = (const float*)d_in[7];
    const float* bfc = (const float*)d_in[8];
    float* out = (float*)d_out;

    cudaFuncSetAttribute(nfold16,  cudaFuncAttributeMaxDynamicSharedMemorySize, DYN16);
    cudaFuncSetAttribute(yc16_mma, cudaFuncAttributeMaxDynamicSharedMemorySize, DYN16);
    cudaFuncSetAttribute(s16_mma,  cudaFuncAttributeMaxDynamicSharedMemorySize, DYN16);

    // OUR index 3 (= ncu capture slot) = merged Y/C GEMM.
    split_all<<<(N4_ALL + 255) / 256, 256>>>(x, Wq, Wk, Wv, Wfc);        // 0
    nfold16<<<dim3(8, 8, 2), NTHR16, DYN16>>>();                          // 1: N1, N2
    gemv_ur<<<256, 256>>>(Wq, bk, Wfc, bv);                               // 2: u, r2
    yc16_mma<<<dim3(8, 128, 2), NTHR16, DYN16>>>();                       // 3: Y + C <- profiled
    gemv_c<<<B_ * T_ / 8, 256>>>(x);                                      // 4: c
    s16_mma<<<dim3(8, 8, 16), NTHR16, DYN16>>>();                         // 5: S
    smdot_kernel<<<(B_ * T_) / 8, 256>>>();                               // 6
    final_kernel<<<B_, 256>>>(bfc, out);                                  // 7
}